// round 15
// baseline (speedup 1.0000x reference)
#include <cuda_runtime.h>
#include <math.h>
#include <stdint.h>

#define N_NODES 100000
#define N_EDGES 3200000
#define K_IN    1433
#define C1      16
#define NTOT_F  143300000u

// ---------------- scratch (static device globals; no allocation) ------------
__device__ __align__(16) int   g_cnt[N_NODES];
__device__ __align__(16) int   g_off[N_NODES + 4];
__device__ __align__(16) int   g_pos[N_NODES];
__device__ __align__(16) float g_dinv[N_NODES];
__device__ __align__(16) int   g_ecol[N_EDGES];
__device__ __align__(16) float g_h1[N_NODES * 16];
__device__ __align__(16) float g_h2[N_NODES * 8];

// ---------------- degree / CSR build ---------------------------------------
__global__ void k_zero_cnt() {
    int i = blockIdx.x * blockDim.x + threadIdx.x;
    if (i * 4 < N_NODES) ((int4*)g_cnt)[i] = make_int4(0, 0, 0, 0);
}

__global__ void k_count(const int* __restrict__ row) {
    int i = blockIdx.x * blockDim.x + threadIdx.x;
    if (i * 8 >= N_EDGES) return;
    int4 r0 = ((const int4*)row)[2 * i];
    int4 r1 = ((const int4*)row)[2 * i + 1];
    atomicAdd(&g_cnt[r0.x], 1);
    atomicAdd(&g_cnt[r0.y], 1);
    atomicAdd(&g_cnt[r0.z], 1);
    atomicAdd(&g_cnt[r0.w], 1);
    atomicAdd(&g_cnt[r1.x], 1);
    atomicAdd(&g_cnt[r1.y], 1);
    atomicAdd(&g_cnt[r1.z], 1);
    atomicAdd(&g_cnt[r1.w], 1);
}

__global__ void k_scan() {
    const int T = 1024, ACT = 1000, CH4 = 25;
    int t = threadIdx.x;
    __shared__ int ps[T];
    int sum = 0;
    if (t < ACT) {
        const int4* c4 = (const int4*)g_cnt + t * CH4;
#pragma unroll
        for (int i = 0; i < CH4; i++) { int4 v = c4[i]; sum += v.x + v.y + v.z + v.w; }
    }
    ps[t] = sum;
    __syncthreads();
    for (int off = 1; off < T; off <<= 1) {
        int v = (t >= off) ? ps[t - off] : 0;
        __syncthreads();
        ps[t] += v;
        __syncthreads();
    }
    if (t < ACT) {
        int run = (t > 0) ? ps[t - 1] : 0;
        const int4* c4 = (const int4*)g_cnt + t * CH4;
        int4*   o4 = (int4*)g_off + t * CH4;
        int4*   p4 = (int4*)g_pos + t * CH4;
        float4* d4 = (float4*)g_dinv + t * CH4;
#pragma unroll 5
        for (int i = 0; i < CH4; i++) {
            int4 v = c4[i];
            int4 o;
            o.x = run; o.y = o.x + v.x; o.z = o.y + v.y; o.w = o.z + v.z;
            run = o.w + v.w;
            o4[i] = o; p4[i] = o;
            float4 dv;
            dv.x = rsqrtf((float)(v.x + 1)); dv.y = rsqrtf((float)(v.y + 1));
            dv.z = rsqrtf((float)(v.z + 1)); dv.w = rsqrtf((float)(v.w + 1));
            d4[i] = dv;
        }
        if (t == ACT - 1) g_off[N_NODES] = run;
    }
}

__global__ void k_place(const int* __restrict__ row, const int* __restrict__ col) {
    int i = blockIdx.x * blockDim.x + threadIdx.x;
    if (i * 8 >= N_EDGES) return;
    int4 r0 = ((const int4*)row)[2 * i];
    int4 r1 = ((const int4*)row)[2 * i + 1];
    int4 c0 = ((const int4*)col)[2 * i];
    int4 c1 = ((const int4*)col)[2 * i + 1];
    int p0 = atomicAdd(&g_pos[r0.x], 1);
    int p1 = atomicAdd(&g_pos[r0.y], 1);
    int p2 = atomicAdd(&g_pos[r0.z], 1);
    int p3 = atomicAdd(&g_pos[r0.w], 1);
    int p4 = atomicAdd(&g_pos[r1.x], 1);
    int p5 = atomicAdd(&g_pos[r1.y], 1);
    int p6 = atomicAdd(&g_pos[r1.z], 1);
    int p7 = atomicAdd(&g_pos[r1.w], 1);
    g_ecol[p0] = c0.x;
    g_ecol[p1] = c0.y;
    g_ecol[p2] = c0.z;
    g_ecol[p3] = c0.w;
    g_ecol[p4] = c1.x;
    g_ecol[p5] = c1.y;
    g_ecol[p6] = c1.z;
    g_ecol[p7] = c1.w;
}

// ---- GEMM1: warp-private pipelines + 16B cp.async on 16-k chunks ------------
// Warp owns 96 rows, 2 private stages. Tile = 16 k. Per row per tile: 5 x cp16
// covering [16c - o, 16c + 20 - o) (o = row&3 keeps src 16B-aligned).
// Slot base = perm(r)*20 floats, perm(r) = (r&3)*24 + (r>>2). Read index
// = 20*perm + b + k == 20a + b + k (mod 32): conflict-free for all k, s.
// Each thread computes exactly the rows its own cps loaded (no cross-lane dep).
#define G1_BLOCK 256
#define G1_MT    768
#define G1_GRID  131
#define G1_NT    90                 // 89 full 16-k tiles + tail (k 1424..1432)
#define RPW      96
#define SLOT_F   20
#define STG_F    (RPW * SLOT_F)     // 1920 floats = 7680 B
#define STAGES   2
#define WS_PAD_K 1440
#define WS_FLOATS (WS_PAD_K * C1)   // 23040, rows 1433.. zeroed
#define G1_SMEM_FLOATS (WS_FLOATS + 8 * STAGES * STG_F)
#define G1_SMEM_BYTES  (G1_SMEM_FLOATS * 4)   // 215,040 B

__device__ __forceinline__ void ffma2(unsigned long long& d,
                                      unsigned long long a,
                                      unsigned long long b) {
    asm("fma.rn.f32x2 %0, %1, %2, %0;" : "+l"(d) : "l"(a), "l"(b));
}
__device__ __forceinline__ void cp16(unsigned dst, const float* src) {
    asm volatile("cp.async.cg.shared.global [%0], [%1], 16;" :: "r"(dst), "l"(src));
}
__device__ __forceinline__ void cp_commit() {
    asm volatile("cp.async.commit_group;");
}
__device__ __forceinline__ void cp_wait1() {
    asm volatile("cp.async.wait_group 1;");
}

__global__ void __launch_bounds__(G1_BLOCK, 1)
k_gemm1(const float* __restrict__ x, const float* __restrict__ W1) {
    extern __shared__ float sm[];
    float* ws = sm;                          // [1440 * 16]
    float* xs = sm + WS_FLOATS;              // [8 warps][2 stages][1920]

    const int tid  = threadIdx.x;
    const int w    = tid >> 5;
    const int lane = tid & 31;
    const int b    = lane & 3;
    const int m0   = blockIdx.x * G1_MT;

    // W1 -> smem, zero-pad rows 1433..1439 (single block barrier in kernel)
    {
        const float4* W4  = (const float4*)W1;
        float4*       ws4 = (float4*)ws;
        const int nW = K_IN * C1 / 4;
        const int nP = WS_FLOATS / 4;
        for (int i = tid; i < nP; i += G1_BLOCK) {
            float4 v = make_float4(0.f, 0.f, 0.f, 0.f);
            if (i < nW) v = W4[i];
            ws4[i] = v;
        }
    }

    // per-thread row invariants: rows lane, lane+32, lane+64 of warp's block
    float* wxs = xs + w * (STAGES * STG_F);
    const unsigned wxs_u32 = (unsigned)__cvta_generic_to_shared(wxs);
    const float* srcp[3];
    unsigned dstp[3], fb[3];
    int xbase[3];
#pragma unroll
    for (int s = 0; s < 3; s++) {
        int r = lane + 32 * s;
        int grow = m0 + RPW * w + r;
        if (grow > N_NODES - 1) grow = N_NODES - 1;   // clamp; masked at store
        int o = grow & 3;
        fb[s]   = (unsigned)grow * (unsigned)K_IN - (unsigned)o;  // 16B-aligned
        srcp[s] = x + fb[s];
        int perm = (r & 3) * 24 + (r >> 2);
        dstp[s]  = wxs_u32 + (unsigned)perm * (SLOT_F * 4);
        xbase[s] = perm * SLOT_F + b;   // unclamped rows: o == b
    }

    unsigned long long acc2[3][8];
#pragma unroll
    for (int r = 0; r < 3; r++)
#pragma unroll
        for (int c = 0; c < 8; c++) acc2[r][c] = 0ull;

    __syncthreads();   // ws visible; warps decouple from here on

    // prologue: issue tiles 0, 1 (both fully in-bounds)
#pragma unroll
    for (int t = 0; t < 2; t++) {
        unsigned stoff = (unsigned)(t & 1) * (STG_F * 4);
#pragma unroll
        for (int s = 0; s < 3; s++) {
            unsigned d0 = dstp[s] + stoff;
            const float* sp = srcp[s] + 16 * t;
#pragma unroll
            for (int j = 0; j < 5; j++) cp16(d0 + 16u * j, sp + 4 * j);
        }
        cp_commit();
    }

    for (int t = 0; t < G1_NT; t++) {
        cp_wait1();            // own group for tile t done (t+1 in flight)
        __syncwarp();

        const float* xb = wxs + (t & 1) * STG_F;
#pragma unroll
        for (int k = 0; k < 16; k++) {
            const ulonglong2* wrow = (const ulonglong2*)(ws + (t * 16 + k) * C1);
            ulonglong2 wa = wrow[0], wb = wrow[1], wc = wrow[2], wd = wrow[3];
#pragma unroll
            for (int r = 0; r < 3; r++) {
                float xv = xb[xbase[r] + k];
                unsigned long long xv2;
                asm("mov.b64 %0, {%1, %1};" : "=l"(xv2) : "f"(xv));
                ffma2(acc2[r][0], xv2, wa.x);
                ffma2(acc2[r][1], xv2, wa.y);
                ffma2(acc2[r][2], xv2, wb.x);
                ffma2(acc2[r][3], xv2, wb.y);
                ffma2(acc2[r][4], xv2, wc.x);
                ffma2(acc2[r][5], xv2, wc.y);
                ffma2(acc2[r][6], xv2, wd.x);
                ffma2(acc2[r][7], xv2, wd.y);
            }
        }

        // issue tile t+2 into the stage just consumed
        int tn = t + 2;
        if (tn < G1_NT) {
            unsigned stoff = (unsigned)(tn & 1) * (STG_F * 4);
            if (tn < G1_NT - 1) {
#pragma unroll
                for (int s = 0; s < 3; s++) {
                    unsigned d0 = dstp[s] + stoff;
                    const float* sp = srcp[s] + 16 * tn;
#pragma unroll
                    for (int j = 0; j < 5; j++) cp16(d0 + 16u * j, sp + 4 * j);
                }
            } else {
                // tail tile: guard against reading past the end of x.
                // Skipped floats only meet zero-padded W rows (k > 1432).
#pragma unroll
                for (int s = 0; s < 3; s++) {
                    unsigned d0 = dstp[s] + stoff;
                    const float* sp = srcp[s] + 16 * tn;
#pragma unroll
                    for (int j = 0; j < 5; j++) {
                        unsigned gf = fb[s] + 16u * (unsigned)tn + 4u * j;
                        if (gf + 4u <= NTOT_F) cp16(d0 + 16u * j, sp + 4 * j);
                    }
                }
            }
        }
        cp_commit();
    }

    // store h1 (rows lane+32r of this warp's 96-row block)
#pragma unroll
    for (int r = 0; r < 3; r++) {
        int m = m0 + RPW * w + lane + 32 * r;
        if (m < N_NODES) {
            float4* o = (float4*)(g_h1 + (size_t)m * 16);
#pragma unroll
            for (int p = 0; p < 4; p++) {
                float2 f0, f1;
                asm("mov.b64 {%0, %1}, %2;" : "=f"(f0.x), "=f"(f0.y) : "l"(acc2[r][2 * p]));
                asm("mov.b64 {%0, %1}, %2;" : "=f"(f1.x), "=f"(f1.y) : "l"(acc2[r][2 * p + 1]));
                o[p] = make_float4(f0.x, f0.y, f1.x, f1.y);
            }
        }
    }
}

// -------- aggregation 1 + bias + relu + GEMM2 fused: ONE WARP PER NODE -------
__global__ void __launch_bounds__(256)
k_agg1(const float* __restrict__ b1, const float* __restrict__ W2) {
    __shared__ float w2s[16 * 7];
    if (threadIdx.x < 16 * 7) w2s[threadIdx.x] = W2[threadIdx.x];
    __syncthreads();

    int g = (blockIdx.x * blockDim.x + threadIdx.x) >> 5;
    if (g >= N_NODES) return;
    int lane = threadIdx.x & 31;
    int e = lane >> 2, q = lane & 3;

    int s = g_off[g];
    int deg = g_off[g + 1] - s;
    const int* cols = g_ecol + s;

    float4 acc = make_float4(0.f, 0.f, 0.f, 0.f);
    for (int i = e; i < deg; i += 8) {
        int c = __ldg(cols + i);
        float dw = g_dinv[c];
        float4 hv = *(const float4*)(g_h1 + (size_t)c * 16 + q * 4);
        acc.x += hv.x * dw; acc.y += hv.y * dw;
        acc.z += hv.z * dw; acc.w += hv.w * dw;
    }

#pragma unroll
    for (int o = 16; o >= 4; o >>= 1) {
        acc.x += __shfl_xor_sync(0xffffffffu, acc.x, o);
        acc.y += __shfl_xor_sync(0xffffffffu, acc.y, o);
        acc.z += __shfl_xor_sync(0xffffffffu, acc.z, o);
        acc.w += __shfl_xor_sync(0xffffffffu, acc.w, o);
    }

    float di = g_dinv[g];
    float4 self = *(const float4*)(g_h1 + (size_t)g * 16 + q * 4);
    float4 bb   = ((const float4*)b1)[q];
    float v0 = fmaxf(bb.x + di * (acc.x + di * self.x), 0.f);
    float v1 = fmaxf(bb.y + di * (acc.y + di * self.y), 0.f);
    float v2 = fmaxf(bb.z + di * (acc.z + di * self.z), 0.f);
    float v3 = fmaxf(bb.w + di * (acc.w + di * self.w), 0.f);

    float h2a[7];
    const float* w2r = w2s + (4 * q) * 7;
#pragma unroll
    for (int c2 = 0; c2 < 7; c2++)
        h2a[c2] = v0 * w2r[c2] + v1 * w2r[7 + c2] + v2 * w2r[14 + c2] + v3 * w2r[21 + c2];
#pragma unroll
    for (int o = 1; o <= 2; o <<= 1)
#pragma unroll
        for (int c2 = 0; c2 < 7; c2++)
            h2a[c2] += __shfl_xor_sync(0xffffffffu, h2a[c2], o);

    if (lane == 0) {
        float4* o4 = (float4*)(g_h2 + (size_t)g * 8);
        o4[0] = make_float4(h2a[0], h2a[1], h2a[2], h2a[3]);
        o4[1] = make_float4(h2a[4], h2a[5], h2a[6], 0.f);
    }
}

// -------- aggregation 2 + bias + log_softmax: ONE WARP PER NODE --------------
__global__ void __launch_bounds__(256)
k_agg2(const float* __restrict__ b2, float* __restrict__ out) {
    int g = (blockIdx.x * blockDim.x + threadIdx.x) >> 5;
    if (g >= N_NODES) return;
    int lane = threadIdx.x & 31;
    int e = lane >> 2, q = lane & 3;

    int s = g_off[g];
    int deg = g_off[g + 1] - s;
    const int* cols = g_ecol + s;

    float a0 = 0.f, a1 = 0.f;
    for (int i = e; i < deg; i += 8) {
        int c = __ldg(cols + i);
        float dw = g_dinv[c];
        float2 hv = *(const float2*)(g_h2 + (size_t)c * 8 + q * 2);
        a0 += hv.x * dw;
        a1 += hv.y * dw;
    }
#pragma unroll
    for (int o = 16; o >= 4; o >>= 1) {
        a0 += __shfl_xor_sync(0xffffffffu, a0, o);
        a1 += __shfl_xor_sync(0xffffffffu, a1, o);
    }

    float di = g_dinv[g];
    float dd = di * di;
    float2 self = *(const float2*)(g_h2 + (size_t)g * 8 + q * 2);
    float bb0 = b2[2 * q];
    float bb1 = (q < 3) ? b2[2 * q + 1] : 0.f;
    a0 = bb0 + di * a0 + dd * self.x;
    a1 = bb1 + di * a1 + dd * self.y;

    float m = (q == 3) ? a0 : fmaxf(a0, a1);
    m = fmaxf(m, __shfl_xor_sync(0xffffffffu, m, 1, 4));
    m = fmaxf(m, __shfl_xor_sync(0xffffffffu, m, 2, 4));
    float e0 = expf(a0 - m);
    float e1 = (q == 3) ? 0.f : expf(a1 - m);
    float ss = e0 + e1;
    ss += __shfl_xor_sync(0xffffffffu, ss, 1, 4);
    ss += __shfl_xor_sync(0xffffffffu, ss, 2, 4);
    float ls = m + logf(ss);

    if (e == 0) {
        out[(size_t)g * 7 + 2 * q] = a0 - ls;
        if (q < 3) out[(size_t)g * 7 + 2 * q + 1] = a1 - ls;
    }
}

// ---------------- launch ------------------------------------------------------
static cudaStream_t s_csr = 0;
static cudaEvent_t  ev_fork = 0, ev_join = 0;

extern "C" void kernel_launch(void* const* d_in, const int* in_sizes, int n_in,
                              void* d_out, int out_size) {
    const float* x   = (const float*)d_in[0];
    const int*   row = (const int*)  d_in[1];
    const int*   col = (const int*)  d_in[2];
    const float* W1  = (const float*)d_in[3];
    const float* b1  = (const float*)d_in[4];
    const float* W2  = (const float*)d_in[5];
    const float* b2  = (const float*)d_in[6];
    float* out = (float*)d_out;

    if (!s_csr) {
        cudaStreamCreateWithFlags(&s_csr, cudaStreamNonBlocking);
        cudaEventCreateWithFlags(&ev_fork, cudaEventDisableTiming);
        cudaEventCreateWithFlags(&ev_join, cudaEventDisableTiming);
        cudaFuncSetAttribute(k_gemm1, cudaFuncAttributeMaxDynamicSharedMemorySize,
                             G1_SMEM_BYTES);
    }

    // fork: CSR chain onto side stream (overlaps with GEMM1)
    cudaEventRecord(ev_fork, 0);
    cudaStreamWaitEvent(s_csr, ev_fork, 0);

    k_zero_cnt<<<(N_NODES / 4 + 255) / 256, 256, 0, s_csr>>>();
    k_count   <<<(N_EDGES / 8 + 255) / 256, 256, 0, s_csr>>>(row);
    k_scan    <<<1, 1024, 0, s_csr>>>();

    // main stream: GEMM1 (4th submission -> profiled slot)
    k_gemm1<<<G1_GRID, G1_BLOCK, G1_SMEM_BYTES>>>(x, W1);

    k_place<<<(N_EDGES / 8 + 255) / 256, 256, 0, s_csr>>>(row, col);

    // join: aggregation needs both CSR and h1
    cudaEventRecord(ev_join, s_csr);
    cudaStreamWaitEvent(0, ev_join, 0);

    k_agg1<<<(N_NODES * 32 + 255) / 256, 256>>>(b1, W2);
    k_agg2<<<(N_NODES * 32 + 255) / 256, 256>>>(b2, out);
}

// round 16
// speedup vs baseline: 1.0879x; 1.0879x over previous
#include <cuda_runtime.h>
#include <math.h>
#include <stdint.h>

#define N_NODES 100000
#define N_EDGES 3200000
#define K_IN    1433
#define C1      16

// ---------------- scratch (static device globals; no allocation) ------------
__device__ __align__(16) int   g_cnt[N_NODES];
__device__ __align__(16) int   g_off[N_NODES + 4];
__device__ __align__(16) int   g_pos[N_NODES];
__device__ __align__(16) float g_dinv[N_NODES];
__device__ __align__(16) int   g_ecol[N_EDGES];
__device__ __align__(16) float g_h1[N_NODES * 16];
__device__ __align__(16) float g_h2[N_NODES * 8];

// ---------------- degree / CSR build ---------------------------------------
__global__ void k_zero_cnt() {
    int i = blockIdx.x * blockDim.x + threadIdx.x;
    if (i * 4 < N_NODES) ((int4*)g_cnt)[i] = make_int4(0, 0, 0, 0);
}

__global__ void k_count(const int* __restrict__ row) {
    int i = blockIdx.x * blockDim.x + threadIdx.x;
    if (i * 8 >= N_EDGES) return;
    int4 r0 = ((const int4*)row)[2 * i];
    int4 r1 = ((const int4*)row)[2 * i + 1];
    atomicAdd(&g_cnt[r0.x], 1);
    atomicAdd(&g_cnt[r0.y], 1);
    atomicAdd(&g_cnt[r0.z], 1);
    atomicAdd(&g_cnt[r0.w], 1);
    atomicAdd(&g_cnt[r1.x], 1);
    atomicAdd(&g_cnt[r1.y], 1);
    atomicAdd(&g_cnt[r1.z], 1);
    atomicAdd(&g_cnt[r1.w], 1);
}

__global__ void k_scan() {
    const int T = 1024, ACT = 1000, CH4 = 25;
    int t = threadIdx.x;
    __shared__ int ps[T];
    int sum = 0;
    if (t < ACT) {
        const int4* c4 = (const int4*)g_cnt + t * CH4;
#pragma unroll
        for (int i = 0; i < CH4; i++) { int4 v = c4[i]; sum += v.x + v.y + v.z + v.w; }
    }
    ps[t] = sum;
    __syncthreads();
    for (int off = 1; off < T; off <<= 1) {
        int v = (t >= off) ? ps[t - off] : 0;
        __syncthreads();
        ps[t] += v;
        __syncthreads();
    }
    if (t < ACT) {
        int run = (t > 0) ? ps[t - 1] : 0;
        const int4* c4 = (const int4*)g_cnt + t * CH4;
        int4*   o4 = (int4*)g_off + t * CH4;
        int4*   p4 = (int4*)g_pos + t * CH4;
        float4* d4 = (float4*)g_dinv + t * CH4;
#pragma unroll 5
        for (int i = 0; i < CH4; i++) {
            int4 v = c4[i];
            int4 o;
            o.x = run; o.y = o.x + v.x; o.z = o.y + v.y; o.w = o.z + v.z;
            run = o.w + v.w;
            o4[i] = o; p4[i] = o;
            float4 dv;
            dv.x = rsqrtf((float)(v.x + 1)); dv.y = rsqrtf((float)(v.y + 1));
            dv.z = rsqrtf((float)(v.z + 1)); dv.w = rsqrtf((float)(v.w + 1));
            d4[i] = dv;
        }
        if (t == ACT - 1) g_off[N_NODES] = run;
    }
}

__global__ void k_place(const int* __restrict__ row, const int* __restrict__ col) {
    int i = blockIdx.x * blockDim.x + threadIdx.x;
    if (i * 8 >= N_EDGES) return;
    int4 r0 = ((const int4*)row)[2 * i];
    int4 r1 = ((const int4*)row)[2 * i + 1];
    int4 c0 = ((const int4*)col)[2 * i];
    int4 c1 = ((const int4*)col)[2 * i + 1];
    int p0 = atomicAdd(&g_pos[r0.x], 1);
    int p1 = atomicAdd(&g_pos[r0.y], 1);
    int p2 = atomicAdd(&g_pos[r0.z], 1);
    int p3 = atomicAdd(&g_pos[r0.w], 1);
    int p4 = atomicAdd(&g_pos[r1.x], 1);
    int p5 = atomicAdd(&g_pos[r1.y], 1);
    int p6 = atomicAdd(&g_pos[r1.z], 1);
    int p7 = atomicAdd(&g_pos[r1.w], 1);
    g_ecol[p0] = c0.x;
    g_ecol[p1] = c0.y;
    g_ecol[p2] = c0.z;
    g_ecol[p3] = c0.w;
    g_ecol[p4] = c1.x;
    g_ecol[p5] = c1.y;
    g_ecol[p6] = c1.z;
    g_ecol[p7] = c1.w;
}

// -------- GEMM1: 12 warp-private cp.async pipelines (no block barriers) ------
// R14 design scaled to 12 warps/CTA (3 per SMSP). Warp owns 64 rows + private
// 4-stage ring. Lane issues k=lane&7 for rows (lane>>3)+4j (j=0..15).
// Slot = k*64 + (r ^ 4k): store/read bank-conflict-free (verified), stage
// exactly 512 floats (max index 7*64+63 = 511).
#define G1_BLOCK 384
#define G1_MT    768                // 12 warps * 64 rows
#define G1_GRID  131                // ceil(100000/768)
#define G1_NT    180                // tile 179: only k=1432 valid (kv guard)
#define RPW      64
#define STAGES   4
#define STG_F    512                // floats per warp-stage (8k * 64 rows)
#define WS_PAD_K 1440
#define WS_FLOATS (WS_PAD_K * C1)   // 23040, rows 1433.. zeroed
#define G1_SMEM_FLOATS (WS_FLOATS + 12 * STAGES * STG_F + 16)
#define G1_SMEM_BYTES  (G1_SMEM_FLOATS * 4)   // 190,528 B

__device__ __forceinline__ void ffma2(unsigned long long& d,
                                      unsigned long long a,
                                      unsigned long long b) {
    asm("fma.rn.f32x2 %0, %1, %2, %0;" : "+l"(d) : "l"(a), "l"(b));
}
__device__ __forceinline__ void cp_async4(unsigned dst, const float* src) {
    asm volatile("cp.async.ca.shared.global [%0], [%1], 4;" :: "r"(dst), "l"(src));
}
__device__ __forceinline__ void cp_commit() {
    asm volatile("cp.async.commit_group;");
}
__device__ __forceinline__ void cp_wait2() {
    asm volatile("cp.async.wait_group 2;");
}

__global__ void __launch_bounds__(G1_BLOCK, 1)
k_gemm1(const float* __restrict__ x, const float* __restrict__ W1) {
    extern __shared__ float sm[];
    float* ws = sm;                          // [1440 * 16]
    float* xs = sm + WS_FLOATS;              // [12 warps][4 stages][512]

    const int tid  = threadIdx.x;
    const int w    = tid >> 5;
    const int lane = tid & 31;
    const int kk   = lane & 7;               // this lane's copy-k
    const int rowb = lane >> 3;              // 0..3
    const int m0   = blockIdx.x * G1_MT;

    // W1 -> smem, zero-pad rows 1433..1439 (single block barrier in kernel)
    {
        const float4* W4  = (const float4*)W1;
        float4*       ws4 = (float4*)ws;
        const int nW = K_IN * C1 / 4;
        const int nP = WS_FLOATS / 4;
        for (int i = tid; i < nP; i += G1_BLOCK) {
            float4 v = make_float4(0.f, 0.f, 0.f, 0.f);
            if (i < nW) v = W4[i];
            ws4[i] = v;
        }
    }

    // per-lane global source offsets for the 16 copies (rows rowb+4j)
    unsigned offu[16];
#pragma unroll
    for (int j = 0; j < 16; j++) {
        int grow = m0 + RPW * w + rowb + 4 * j;
        if (grow > N_NODES - 1) grow = N_NODES - 1;      // clamp; masked at store
        offu[j] = (unsigned)grow * K_IN + kk;
    }
    float* wxs = xs + w * (STAGES * STG_F);
    const unsigned wxs_u32 = (unsigned)__cvta_generic_to_shared(wxs);
    const unsigned dstc = wxs_u32 + (unsigned)(kk * RPW + rowb) * 4u;

    unsigned long long acc2[2][8];
#pragma unroll
    for (int r = 0; r < 2; r++)
#pragma unroll
        for (int c = 0; c < 8; c++) acc2[r][c] = 0ull;

    __syncthreads();   // ws visible; warps decouple from here on

    // prologue: issue tiles 0..2 (all k valid: t < 179)
#pragma unroll
    for (int t = 0; t < 3; t++) {
        unsigned d0 = dstc + (unsigned)(t * STG_F) * 4u;
        const float* src = x + 8 * t;
#pragma unroll
        for (int j = 0; j < 16; j++)
            cp_async4(d0 + 16u * (unsigned)(j ^ kk), src + offu[j]);
        cp_commit();
    }

    for (int t = 0; t < G1_NT; t++) {
        cp_wait2();            // own group for tile t done
        __syncwarp();          // make lane-mates' staging writes visible

        // issue tile t+3 into stage (t+3)&3
        if (t + 3 < G1_NT) {
            int tn = t + 3;
            unsigned d0 = dstc + (unsigned)((tn & 3) * STG_F) * 4u;
            const float* src = x + 8 * tn;
            bool kv = (8 * tn + kk) < K_IN;   // false only for tn=179, kk>0
            if (kv) {
#pragma unroll
                for (int j = 0; j < 16; j++)
                    cp_async4(d0 + 16u * (unsigned)(j ^ kk), src + offu[j]);
            }
        }
        cp_commit();

        const float* xb = wxs + (t & 3) * STG_F;
#pragma unroll
        for (int k = 0; k < 8; k++) {
            const ulonglong2* wrow = (const ulonglong2*)(ws + (t * 8 + k) * C1);
            ulonglong2 wa = wrow[0], wb = wrow[1], wc = wrow[2], wd = wrow[3];
            const int lx = (lane ^ (4 * k)) + k * RPW;
#pragma unroll
            for (int r = 0; r < 2; r++) {
                float xv = xb[lx + 32 * r];
                unsigned long long xv2;
                asm("mov.b64 %0, {%1, %1};" : "=l"(xv2) : "f"(xv));
                ffma2(acc2[r][0], xv2, wa.x);
                ffma2(acc2[r][1], xv2, wa.y);
                ffma2(acc2[r][2], xv2, wb.x);
                ffma2(acc2[r][3], xv2, wb.y);
                ffma2(acc2[r][4], xv2, wc.x);
                ffma2(acc2[r][5], xv2, wc.y);
                ffma2(acc2[r][6], xv2, wd.x);
                ffma2(acc2[r][7], xv2, wd.y);
            }
        }
    }

    // store h1 (rows lane, lane+32 of this warp's 64-row block)
#pragma unroll
    for (int r = 0; r < 2; r++) {
        int m = m0 + RPW * w + lane + 32 * r;
        if (m < N_NODES) {
            float4* o = (float4*)(g_h1 + (size_t)m * 16);
#pragma unroll
            for (int p = 0; p < 4; p++) {
                float2 f0, f1;
                asm("mov.b64 {%0, %1}, %2;" : "=f"(f0.x), "=f"(f0.y) : "l"(acc2[r][2 * p]));
                asm("mov.b64 {%0, %1}, %2;" : "=f"(f1.x), "=f"(f1.y) : "l"(acc2[r][2 * p + 1]));
                o[p] = make_float4(f0.x, f0.y, f1.x, f1.y);
            }
        }
    }
}

// -------- aggregation 1 + bias + relu + GEMM2 fused: ONE WARP PER NODE -------
__global__ void __launch_bounds__(256)
k_agg1(const float* __restrict__ b1, const float* __restrict__ W2) {
    __shared__ float w2s[16 * 7];
    if (threadIdx.x < 16 * 7) w2s[threadIdx.x] = W2[threadIdx.x];
    __syncthreads();

    int g = (blockIdx.x * blockDim.x + threadIdx.x) >> 5;
    if (g >= N_NODES) return;
    int lane = threadIdx.x & 31;
    int e = lane >> 2, q = lane & 3;

    int s = g_off[g];
    int deg = g_off[g + 1] - s;
    const int* cols = g_ecol + s;

    float4 acc = make_float4(0.f, 0.f, 0.f, 0.f);
    for (int i = e; i < deg; i += 8) {
        int c = __ldg(cols + i);
        float dw = g_dinv[c];
        float4 hv = *(const float4*)(g_h1 + (size_t)c * 16 + q * 4);
        acc.x += hv.x * dw; acc.y += hv.y * dw;
        acc.z += hv.z * dw; acc.w += hv.w * dw;
    }

#pragma unroll
    for (int o = 16; o >= 4; o >>= 1) {
        acc.x += __shfl_xor_sync(0xffffffffu, acc.x, o);
        acc.y += __shfl_xor_sync(0xffffffffu, acc.y, o);
        acc.z += __shfl_xor_sync(0xffffffffu, acc.z, o);
        acc.w += __shfl_xor_sync(0xffffffffu, acc.w, o);
    }

    float di = g_dinv[g];
    float4 self = *(const float4*)(g_h1 + (size_t)g * 16 + q * 4);
    float4 bb   = ((const float4*)b1)[q];
    float v0 = fmaxf(bb.x + di * (acc.x + di * self.x), 0.f);
    float v1 = fmaxf(bb.y + di * (acc.y + di * self.y), 0.f);
    float v2 = fmaxf(bb.z + di * (acc.z + di * self.z), 0.f);
    float v3 = fmaxf(bb.w + di * (acc.w + di * self.w), 0.f);

    float h2a[7];
    const float* w2r = w2s + (4 * q) * 7;
#pragma unroll
    for (int c2 = 0; c2 < 7; c2++)
        h2a[c2] = v0 * w2r[c2] + v1 * w2r[7 + c2] + v2 * w2r[14 + c2] + v3 * w2r[21 + c2];
#pragma unroll
    for (int o = 1; o <= 2; o <<= 1)
#pragma unroll
        for (int c2 = 0; c2 < 7; c2++)
            h2a[c2] += __shfl_xor_sync(0xffffffffu, h2a[c2], o);

    if (lane == 0) {
        float4* o4 = (float4*)(g_h2 + (size_t)g * 8);
        o4[0] = make_float4(h2a[0], h2a[1], h2a[2], h2a[3]);
        o4[1] = make_float4(h2a[4], h2a[5], h2a[6], 0.f);
    }
}

// -------- aggregation 2 + bias + log_softmax: ONE WARP PER NODE --------------
__global__ void __launch_bounds__(256)
k_agg2(const float* __restrict__ b2, float* __restrict__ out) {
    int g = (blockIdx.x * blockDim.x + threadIdx.x) >> 5;
    if (g >= N_NODES) return;
    int lane = threadIdx.x & 31;
    int e = lane >> 2, q = lane & 3;

    int s = g_off[g];
    int deg = g_off[g + 1] - s;
    const int* cols = g_ecol + s;

    float a0 = 0.f, a1 = 0.f;
    for (int i = e; i < deg; i += 8) {
        int c = __ldg(cols + i);
        float dw = g_dinv[c];
        float2 hv = *(const float2*)(g_h2 + (size_t)c * 8 + q * 2);
        a0 += hv.x * dw;
        a1 += hv.y * dw;
    }
#pragma unroll
    for (int o = 16; o >= 4; o >>= 1) {
        a0 += __shfl_xor_sync(0xffffffffu, a0, o);
        a1 += __shfl_xor_sync(0xffffffffu, a1, o);
    }

    float di = g_dinv[g];
    float dd = di * di;
    float2 self = *(const float2*)(g_h2 + (size_t)g * 8 + q * 2);
    float bb0 = b2[2 * q];
    float bb1 = (q < 3) ? b2[2 * q + 1] : 0.f;
    a0 = bb0 + di * a0 + dd * self.x;
    a1 = bb1 + di * a1 + dd * self.y;

    float m = (q == 3) ? a0 : fmaxf(a0, a1);
    m = fmaxf(m, __shfl_xor_sync(0xffffffffu, m, 1, 4));
    m = fmaxf(m, __shfl_xor_sync(0xffffffffu, m, 2, 4));
    float e0 = expf(a0 - m);
    float e1 = (q == 3) ? 0.f : expf(a1 - m);
    float ss = e0 + e1;
    ss += __shfl_xor_sync(0xffffffffu, ss, 1, 4);
    ss += __shfl_xor_sync(0xffffffffu, ss, 2, 4);
    float ls = m + logf(ss);

    if (e == 0) {
        out[(size_t)g * 7 + 2 * q] = a0 - ls;
        if (q < 3) out[(size_t)g * 7 + 2 * q + 1] = a1 - ls;
    }
}

// ---------------- launch ------------------------------------------------------
static cudaStream_t s_csr = 0;
static cudaEvent_t  ev_fork = 0, ev_join = 0;

extern "C" void kernel_launch(void* const* d_in, const int* in_sizes, int n_in,
                              void* d_out, int out_size) {
    const float* x   = (const float*)d_in[0];
    const int*   row = (const int*)  d_in[1];
    const int*   col = (const int*)  d_in[2];
    const float* W1  = (const float*)d_in[3];
    const float* b1  = (const float*)d_in[4];
    const float* W2  = (const float*)d_in[5];
    const float* b2  = (const float*)d_in[6];
    float* out = (float*)d_out;

    if (!s_csr) {
        cudaStreamCreateWithFlags(&s_csr, cudaStreamNonBlocking);
        cudaEventCreateWithFlags(&ev_fork, cudaEventDisableTiming);
        cudaEventCreateWithFlags(&ev_join, cudaEventDisableTiming);
        cudaFuncSetAttribute(k_gemm1, cudaFuncAttributeMaxDynamicSharedMemorySize,
                             G1_SMEM_BYTES);
    }

    // fork: CSR chain onto side stream (overlaps with GEMM1)
    cudaEventRecord(ev_fork, 0);
    cudaStreamWaitEvent(s_csr, ev_fork, 0);

    k_zero_cnt<<<(N_NODES / 4 + 255) / 256, 256, 0, s_csr>>>();
    k_count   <<<(N_EDGES / 8 + 255) / 256, 256, 0, s_csr>>>(row);
    k_scan    <<<1, 1024, 0, s_csr>>>();

    // main stream: GEMM1 (4th submission -> profiled slot)
    k_gemm1<<<G1_GRID, G1_BLOCK, G1_SMEM_BYTES>>>(x, W1);

    k_place<<<(N_EDGES / 8 + 255) / 256, 256, 0, s_csr>>>(row, col);

    // join: aggregation needs both CSR and h1
    cudaEventRecord(ev_join, s_csr);
    cudaStreamWaitEvent(0, ev_join, 0);

    k_agg1<<<(N_NODES * 32 + 255) / 256, 256>>>(b1, W2);
    k_agg2<<<(N_NODES * 32 + 255) / 256, 256>>>(b2, out);
}